// round 5
// baseline (speedup 1.0000x reference)
#include <cuda_runtime.h>
#include <cuda_bf16.h>
#include <cstdint>

#define Bq 8
#define Nn 2048
#define Dd 128
#define DE 136            // 128 emb + hsq + ones + 6 pad -> 17 n8-tiles
#define TM 64
#define TK 32
#define NS 3
#define KSPLIT 2
#define NBLK (Bq * (Nn / TM) * KSPLIT)   // 512

// smem strides (bytes), conflict-free for the fragment LDS patterns
#define A_STRIDE 160      // 128B fp32 data + 32B pad (40 words)
#define B_STRIDE 80       // 64B bf16 data + 16B pad (20 words)
#define A_STAGE  (TM * A_STRIDE)          // 10240
#define B_STAGE  (DE * B_STRIDE)          // 10880
#define STAGE_BYTES (A_STAGE + B_STAGE)   // 21120
#define SMEM_BYTES  (NS * STAGE_BYTES)    // 63360

// scratch (no allocation allowed -> device globals)
__device__ float          g_hsq[Bq * Nn];
__device__ __nv_bfloat16  g_HextT[(size_t)Bq * DE * Nn];  // [b][d][j] bf16
__device__ float          g_part[NBLK];
__device__ int            g_done;

__device__ __forceinline__ uint32_t smem_u32(const void* p) {
    uint32_t a;
    asm("{ .reg .u64 t; cvta.to.shared.u64 t, %1; cvt.u32.u64 %0, t; }"
        : "=r"(a) : "l"(p));
    return a;
}
__device__ __forceinline__ void cp16(uint32_t dst, const void* src) {
    asm volatile("cp.async.cg.shared.global [%0], [%1], 16;"
                 :: "r"(dst), "l"(src) : "memory");
}
__device__ __forceinline__ uint32_t packbf(float x, float y) {
    __nv_bfloat162 p = __floats2bfloat162_rn(x, y);
    return *reinterpret_cast<uint32_t*>(&p);
}

// ---------------------------------------------------------------------------
// Kernel 0 (prep): hsq + bf16 transposed extended embedding
//   HextT[b][d][j]:  d<128: h_jd,  d=128: hsq_j,  d=129: 1,  d>=130: 0
// ---------------------------------------------------------------------------
__global__ void k_prep(const float* __restrict__ H) {
    __shared__ float s2[32][137];   // odd stride -> conflict-free column reads
    __shared__ float hq[32];
    const int b = blockIdx.y, j0 = blockIdx.x * 32;
    const int tid = threadIdx.x;    // 256
    if (blockIdx.x == 0 && blockIdx.y == 0 && tid == 0) g_done = 0;

    #pragma unroll
    for (int c = 0; c < 4; c++) {
        int idx = tid + c * 256;            // 1024 float4s
        int j = idx >> 5, d4 = (idx & 31) * 4;
        float4 v = *(const float4*)(H + ((size_t)(b * Nn + j0 + j)) * Dd + d4);
        s2[j][d4 + 0] = v.x; s2[j][d4 + 1] = v.y;
        s2[j][d4 + 2] = v.z; s2[j][d4 + 3] = v.w;
    }
    __syncthreads();

    {   // hsq: warp w -> 4 rows, 8 lanes per row
        const int w = tid >> 5, l = tid & 31;
        const int j = w * 4 + (l >> 3), sub = l & 7;
        float sum = 0.f;
        #pragma unroll
        for (int m = 0; m < 16; m++) {
            float v = s2[j][sub + 8 * m];
            sum += v * v;
        }
        sum += __shfl_xor_sync(0xFFFFFFFFu, sum, 1);
        sum += __shfl_xor_sync(0xFFFFFFFFu, sum, 2);
        sum += __shfl_xor_sync(0xFFFFFFFFu, sum, 4);
        if (sub == 0) { hq[j] = sum; g_hsq[b * Nn + j0 + j] = sum; }
    }
    __syncthreads();

    for (int idx = tid; idx < DE * 8; idx += 256) {
        int d = idx >> 3, jq = (idx & 7) * 4;
        float v[4];
        #pragma unroll
        for (int r = 0; r < 4; r++) {
            int j = jq + r;
            v[r] = (d < 128) ? s2[j][d]
                 : (d == 128) ? hq[j]
                 : (d == 129) ? 1.0f : 0.0f;
        }
        uint2 p;
        p.x = packbf(v[0], v[1]);
        p.y = packbf(v[2], v[3]);
        *(uint2*)&g_HextT[((size_t)(b * DE + d)) * Nn + j0 + jq] = p;
    }
}

// ---------------------------------------------------------------------------
// Kernel 1: bf16 pipelined GEMM + fused epilogue + last-CTA reduction.
// Grid (KSPLIT, 32, 8), 256 thr, 3 CTAs/SM. Warps 4(m)x2(n); warp tile m16.
// ---------------------------------------------------------------------------
__global__ __launch_bounds__(256, 3)
void k_main(const float* __restrict__ A, const float* __restrict__ H,
            float* __restrict__ out) {
    extern __shared__ char smem[];
    __shared__ float s_red[8];
    __shared__ int   s_last;
    const uint32_t sb0 = smem_u32(smem);
    const int tid = threadIdx.x;
    const int wid = tid >> 5, lane = tid & 31;
    const int ks = blockIdx.x, mt = blockIdx.y, b = blockIdx.z;
    const int i0 = mt * TM;
    const int kbase = ks * (Nn / KSPLIT);
    const int NIT = (Nn / KSPLIT) / TK;         // 32

    const int wm = wid >> 1;          // 0..3 -> m offset 16*wm
    const int wn = wid & 1;           // 0..1 -> tiles [9*wn, 9*wn+9) (8 for wn=1)
    const int qr = lane >> 2;         // 0..7
    const int qc = (lane & 3) * 2;    // 0,2,4,6

    const float*         Ag = A + ((size_t)b * Nn + i0) * Nn + kbase;
    const __nv_bfloat16* Bg = g_HextT + ((size_t)b * DE) * Nn + kbase;

    float acc[9][4];
    #pragma unroll
    for (int t = 0; t < 9; t++)
        #pragma unroll
        for (int r = 0; r < 4; r++) acc[t][r] = 0.f;

    auto issue = [&](int it) {
        uint32_t sa = sb0 + (it % NS) * STAGE_BYTES;
        const float* ag = Ag + it * TK;
        #pragma unroll
        for (int c = 0; c < 2; c++) {
            int e = tid + c * 256;                 // 512 chunks
            int row = e >> 3, ch = e & 7;
            cp16(sa + row * A_STRIDE + ch * 16, ag + (size_t)row * Nn + ch * 4);
        }
        uint32_t sbB = sa + A_STAGE;
        const __nv_bfloat16* bg = Bg + it * TK;
        #pragma unroll
        for (int c = 0; c < 3; c++) {
            int e = tid + c * 256;                 // need 544
            if (e < DE * 4) {
                int row = e >> 2, ch = e & 3;
                cp16(sbB + row * B_STRIDE + ch * 16, bg + (size_t)row * Nn + ch * 8);
            }
        }
    };

    // prologue
    #pragma unroll
    for (int p = 0; p < NS - 1; p++) {
        issue(p);
        asm volatile("cp.async.commit_group;" ::: "memory");
    }

    for (int it = 0; it < NIT; it++) {
        if (it + NS - 1 < NIT) issue(it + NS - 1);
        asm volatile("cp.async.commit_group;" ::: "memory");
        asm volatile("cp.async.wait_group %0;" :: "n"(NS - 1) : "memory");
        __syncthreads();

        const char* smA = smem + (it % NS) * STAGE_BYTES;
        const char* smB = smA + A_STAGE;

        #pragma unroll
        for (int k16 = 0; k16 < TK; k16 += 16) {
            const char* ap = smA + (wm * 16 + qr) * A_STRIDE;
            float2 v00 = *(const float2*)(ap + (k16 + qc) * 4);
            float2 v10 = *(const float2*)(ap + 8 * A_STRIDE + (k16 + qc) * 4);
            float2 v01 = *(const float2*)(ap + (k16 + qc + 8) * 4);
            float2 v11 = *(const float2*)(ap + 8 * A_STRIDE + (k16 + qc + 8) * 4);
            uint32_t a0 = packbf(v00.x, v00.y);
            uint32_t a1 = packbf(v10.x, v10.y);
            uint32_t a2 = packbf(v01.x, v01.y);
            uint32_t a3 = packbf(v11.x, v11.y);
            #pragma unroll
            for (int t = 0; t < 9; t++) {
                if (wn == 0 || t < 8) {
                    const int n = (wn * 9 + t) * 8 + qr;
                    uint32_t b0 = *(const uint32_t*)(smB + n * B_STRIDE + (k16 + qc) * 2);
                    uint32_t b1 = *(const uint32_t*)(smB + n * B_STRIDE + (k16 + qc + 8) * 2);
                    asm volatile(
                        "mma.sync.aligned.m16n8k16.row.col.f32.bf16.bf16.f32 "
                        "{%0,%1,%2,%3}, {%4,%5,%6,%7}, {%8,%9}, {%0,%1,%2,%3};\n"
                        : "+f"(acc[t][0]), "+f"(acc[t][1]),
                          "+f"(acc[t][2]), "+f"(acc[t][3])
                        : "r"(a0), "r"(a1), "r"(a2), "r"(a3), "r"(b0), "r"(b1));
                }
            }
        }
        __syncthreads();
    }

    // ---- epilogue: weighted reduction ----
    float tsum = 0.f;
    #pragma unroll
    for (int rr = 0; rr < 2; rr++) {
        const int i = i0 + wm * 16 + qr + rr * 8;
        const float* Hrow = H + ((size_t)(b * Nn + i)) * Dd;
        const float hsq_i = g_hsq[b * Nn + i];
        #pragma unroll
        for (int t = 0; t < 9; t++) {
            if (wn == 0 || t < 8) {
                const int d0 = (wn * 9 + t) * 8 + qc;
                float c0 = acc[t][rr * 2 + 0];
                float c1 = acc[t][rr * 2 + 1];
                float w0, w1;
                if (d0 < 128)       { w0 = -2.f * Hrow[d0]; w1 = -2.f * Hrow[d0 + 1]; }
                else if (d0 == 128) { w0 = 1.f;             w1 = hsq_i; }
                else                { w0 = 0.f;             w1 = 0.f; }
                tsum += c0 * w0 + c1 * w1;
            }
        }
    }
    #pragma unroll
    for (int o = 16; o; o >>= 1) tsum += __shfl_xor_sync(0xFFFFFFFFu, tsum, o);
    if (lane == 0) s_red[wid] = tsum;
    __syncthreads();
    if (tid == 0) {
        float bs = 0.f;
        #pragma unroll
        for (int x = 0; x < 8; x++) bs += s_red[x];
        g_part[(b * (Nn / TM) + mt) * KSPLIT + ks] = bs;
        __threadfence();
        int c = atomicAdd(&g_done, 1);
        s_last = (c == NBLK - 1);
    }
    __syncthreads();

    // ---- last CTA: deterministic final reduction (reuse dynamic smem) ----
    if (s_last) {
        float* s = (float*)smem;
        s[tid]       = *((volatile float*)&g_part[tid]);
        s[tid + 256] = *((volatile float*)&g_part[tid + 256]);
        __syncthreads();
        #pragma unroll
        for (int o = NBLK / 2; o; o >>= 1) {
            if (tid < o) s[tid] += s[tid + o];
            __syncthreads();
        }
        if (tid == 0) out[0] = s[0] / (float)(Bq * Nn);
    }
}

// ---------------------------------------------------------------------------
extern "C" void kernel_launch(void* const* d_in, const int* in_sizes, int n_in,
                              void* d_out, int out_size) {
    const float* adj = (const float*)d_in[0];
    const float* emb = (const float*)d_in[1];

    static bool attr_done = false;
    if (!attr_done) {
        cudaFuncSetAttribute(k_main, cudaFuncAttributeMaxDynamicSharedMemorySize,
                             SMEM_BYTES);
        attr_done = true;
    }

    dim3 gp(Nn / 32, Bq);
    k_prep<<<gp, 256>>>(emb);
    dim3 gm(KSPLIT, Nn / TM, Bq);
    k_main<<<gm, 256, SMEM_BYTES>>>(adj, emb, (float*)d_out);
}

// round 6
// speedup vs baseline: 1.2254x; 1.2254x over previous
#include <cuda_runtime.h>
#include <cuda_bf16.h>
#include <cstdint>

#define Bq 8
#define Nn 2048
#define Dd 128
#define DE 144            // 128 emb + hsq + ones + 14 pad -> 18 n8-tiles
#define TM 128
#define TK 32
#define NS 3
#define KSPLIT 2
#define NBLK (Bq * (Nn / TM) * KSPLIT)   // 256

// smem strides (bytes), conflict-free for fragment LDS patterns
#define A_STRIDE 160      // 128B fp32 data + 32B pad (40 words)
#define B_STRIDE 80       // 64B bf16 data + 16B pad (20 words)
#define A_STAGE  (TM * A_STRIDE)          // 20480
#define B_STAGE  (DE * B_STRIDE)          // 11520
#define STAGE_BYTES (A_STAGE + B_STAGE)   // 32000
#define SMEM_BYTES  (NS * STAGE_BYTES)    // 96000

// scratch (no allocation allowed -> device globals)
__device__ float          g_hsq[Bq * Nn];
__device__ __nv_bfloat16  g_HextT[(size_t)Bq * DE * Nn];  // [b][d][j] bf16
__device__ float          g_part[NBLK];
__device__ int            g_done;

__device__ __forceinline__ uint32_t smem_u32(const void* p) {
    uint32_t a;
    asm("{ .reg .u64 t; cvta.to.shared.u64 t, %1; cvt.u32.u64 %0, t; }"
        : "=r"(a) : "l"(p));
    return a;
}
__device__ __forceinline__ void cp16(uint32_t dst, const void* src) {
    asm volatile("cp.async.cg.shared.global [%0], [%1], 16;"
                 :: "r"(dst), "l"(src) : "memory");
}
__device__ __forceinline__ uint32_t packbf(float x, float y) {
    __nv_bfloat162 p = __floats2bfloat162_rn(x, y);
    return *reinterpret_cast<uint32_t*>(&p);
}

// ---------------------------------------------------------------------------
// Kernel 0 (prep): hsq + bf16 transposed extended embedding
//   HextT[b][d][j]:  d<128: h_jd,  d=128: hsq_j,  d=129: 1,  d>=130: 0
// ---------------------------------------------------------------------------
__global__ void k_prep(const float* __restrict__ H) {
    __shared__ float s2[32][137];   // odd stride -> conflict-free column reads
    __shared__ float hq[32];
    const int b = blockIdx.y, j0 = blockIdx.x * 32;
    const int tid = threadIdx.x;    // 256
    if (blockIdx.x == 0 && blockIdx.y == 0 && tid == 0) g_done = 0;

    #pragma unroll
    for (int c = 0; c < 4; c++) {
        int idx = tid + c * 256;            // 1024 float4s
        int j = idx >> 5, d4 = (idx & 31) * 4;
        float4 v = *(const float4*)(H + ((size_t)(b * Nn + j0 + j)) * Dd + d4);
        s2[j][d4 + 0] = v.x; s2[j][d4 + 1] = v.y;
        s2[j][d4 + 2] = v.z; s2[j][d4 + 3] = v.w;
    }
    __syncthreads();

    {   // hsq: warp w -> 4 rows, 8 lanes per row
        const int w = tid >> 5, l = tid & 31;
        const int j = w * 4 + (l >> 3), sub = l & 7;
        float sum = 0.f;
        #pragma unroll
        for (int m = 0; m < 16; m++) {
            float v = s2[j][sub + 8 * m];
            sum += v * v;
        }
        sum += __shfl_xor_sync(0xFFFFFFFFu, sum, 1);
        sum += __shfl_xor_sync(0xFFFFFFFFu, sum, 2);
        sum += __shfl_xor_sync(0xFFFFFFFFu, sum, 4);
        if (sub == 0) { hq[j] = sum; g_hsq[b * Nn + j0 + j] = sum; }
    }
    __syncthreads();

    for (int idx = tid; idx < DE * 8; idx += 256) {
        int d = idx >> 3, jq = (idx & 7) * 4;
        float v[4];
        #pragma unroll
        for (int r = 0; r < 4; r++) {
            int j = jq + r;
            v[r] = (d < 128) ? s2[j][d]
                 : (d == 128) ? hq[j]
                 : (d == 129) ? 1.0f : 0.0f;
        }
        uint2 p;
        p.x = packbf(v[0], v[1]);
        p.y = packbf(v[2], v[3]);
        *(uint2*)&g_HextT[((size_t)(b * DE + d)) * Nn + j0 + jq] = p;
    }
}

// ---------------------------------------------------------------------------
// Kernel 1: bf16 pipelined GEMM + fused epilogue + last-CTA reduction.
// Grid (KSPLIT, 16, 8), 256 thr, occ 2. Warps 4(m) x 2(n); warp tile m32xn72.
// Single __syncthreads per K-iteration.
// ---------------------------------------------------------------------------
__global__ __launch_bounds__(256, 2)
void k_main(const float* __restrict__ A, const float* __restrict__ H,
            float* __restrict__ out) {
    extern __shared__ char smem[];
    __shared__ float s_red[8];
    __shared__ int   s_last;
    const uint32_t sb0 = smem_u32(smem);
    const int tid = threadIdx.x;
    const int wid = tid >> 5, lane = tid & 31;
    const int ks = blockIdx.x, mt = blockIdx.y, b = blockIdx.z;
    const int i0 = mt * TM;
    const int kbase = ks * (Nn / KSPLIT);
    const int NIT = (Nn / KSPLIT) / TK;         // 32

    const int wm = wid >> 1;          // 0..3 -> m offset 32*wm
    const int wn = wid & 1;           // 0..1 -> tiles [9*wn, 9*wn+9)
    const int qr = lane >> 2;         // 0..7
    const int qc = (lane & 3) * 2;    // 0,2,4,6

    const float*         Ag = A + ((size_t)b * Nn + i0) * Nn + kbase;
    const __nv_bfloat16* Bg = g_HextT + ((size_t)b * DE) * Nn + kbase;

    float acc[2][9][4];
    #pragma unroll
    for (int f = 0; f < 2; f++)
        #pragma unroll
        for (int t = 0; t < 9; t++)
            #pragma unroll
            for (int r = 0; r < 4; r++) acc[f][t][r] = 0.f;

    auto issue = [&](int it) {
        uint32_t sa = sb0 + (it % NS) * STAGE_BYTES;
        const float* ag = Ag + it * TK;
        #pragma unroll
        for (int c = 0; c < 4; c++) {
            int e = tid + c * 256;                 // 1024 chunks
            int row = e >> 3, ch = e & 7;
            cp16(sa + row * A_STRIDE + ch * 16, ag + (size_t)row * Nn + ch * 4);
        }
        uint32_t sbB = sa + A_STAGE;
        const __nv_bfloat16* bg = Bg + it * TK;
        #pragma unroll
        for (int c = 0; c < 3; c++) {
            int e = tid + c * 256;                 // need 576
            if (e < DE * 4) {
                int row = e >> 2, ch = e & 3;
                cp16(sbB + row * B_STRIDE + ch * 16, bg + (size_t)row * Nn + ch * 8);
            }
        }
    };

    // prologue
    #pragma unroll
    for (int p = 0; p < NS - 1; p++) {
        issue(p);
        asm volatile("cp.async.commit_group;" ::: "memory");
    }

    for (int it = 0; it < NIT; it++) {
        // stage it%NS must have landed; all warps done with stage (it-1)%NS
        asm volatile("cp.async.wait_group %0;" :: "n"(NS - 2) : "memory");
        __syncthreads();
        if (it + NS - 1 < NIT) {
            issue(it + NS - 1);                    // overwrites stage (it-1)%NS
            asm volatile("cp.async.commit_group;" ::: "memory");
        }

        const char* smA = smem + (it % NS) * STAGE_BYTES;
        const char* smB = smA + A_STAGE;

        #pragma unroll
        for (int k16 = 0; k16 < TK; k16 += 16) {
            uint32_t a[2][4];
            #pragma unroll
            for (int f = 0; f < 2; f++) {
                const char* ap = smA + (wm * 32 + f * 16 + qr) * A_STRIDE;
                float2 v00 = *(const float2*)(ap + (k16 + qc) * 4);
                float2 v10 = *(const float2*)(ap + 8 * A_STRIDE + (k16 + qc) * 4);
                float2 v01 = *(const float2*)(ap + (k16 + qc + 8) * 4);
                float2 v11 = *(const float2*)(ap + 8 * A_STRIDE + (k16 + qc + 8) * 4);
                a[f][0] = packbf(v00.x, v00.y);
                a[f][1] = packbf(v10.x, v10.y);
                a[f][2] = packbf(v01.x, v01.y);
                a[f][3] = packbf(v11.x, v11.y);
            }
            #pragma unroll
            for (int t = 0; t < 9; t++) {
                const int n = (wn * 9 + t) * 8 + qr;
                uint32_t b0 = *(const uint32_t*)(smB + n * B_STRIDE + (k16 + qc) * 2);
                uint32_t b1 = *(const uint32_t*)(smB + n * B_STRIDE + (k16 + qc + 8) * 2);
                #pragma unroll
                for (int f = 0; f < 2; f++) {
                    asm volatile(
                        "mma.sync.aligned.m16n8k16.row.col.f32.bf16.bf16.f32 "
                        "{%0,%1,%2,%3}, {%4,%5,%6,%7}, {%8,%9}, {%0,%1,%2,%3};\n"
                        : "+f"(acc[f][t][0]), "+f"(acc[f][t][1]),
                          "+f"(acc[f][t][2]), "+f"(acc[f][t][3])
                        : "r"(a[f][0]), "r"(a[f][1]), "r"(a[f][2]), "r"(a[f][3]),
                          "r"(b0), "r"(b1));
                }
            }
        }
    }

    // ---- epilogue: weighted reduction ----
    float tsum = 0.f;
    #pragma unroll
    for (int f = 0; f < 2; f++) {
        #pragma unroll
        for (int rr = 0; rr < 2; rr++) {
            const int i = i0 + wm * 32 + f * 16 + qr + rr * 8;
            const float* Hrow = H + ((size_t)(b * Nn + i)) * Dd;
            const float hsq_i = g_hsq[b * Nn + i];
            #pragma unroll
            for (int t = 0; t < 9; t++) {
                const int d0 = (wn * 9 + t) * 8 + qc;
                float c0 = acc[f][t][rr * 2 + 0];
                float c1 = acc[f][t][rr * 2 + 1];
                float w0, w1;
                if (d0 < 128)       { w0 = -2.f * Hrow[d0]; w1 = -2.f * Hrow[d0 + 1]; }
                else if (d0 == 128) { w0 = 1.f;             w1 = hsq_i; }
                else                { w0 = 0.f;             w1 = 0.f; }
                tsum += c0 * w0 + c1 * w1;
            }
        }
    }
    #pragma unroll
    for (int o = 16; o; o >>= 1) tsum += __shfl_xor_sync(0xFFFFFFFFu, tsum, o);
    if (lane == 0) s_red[wid] = tsum;
    __syncthreads();
    if (tid == 0) {
        float bs = 0.f;
        #pragma unroll
        for (int x = 0; x < 8; x++) bs += s_red[x];
        g_part[(b * (Nn / TM) + mt) * KSPLIT + ks] = bs;
        __threadfence();
        int c = atomicAdd(&g_done, 1);
        s_last = (c == NBLK - 1);
    }
    __syncthreads();

    // ---- last CTA: deterministic final reduction (reuse dynamic smem) ----
    if (s_last) {
        float* s = (float*)smem;
        __threadfence();
        s[tid] = *((volatile float*)&g_part[tid]);
        __syncthreads();
        #pragma unroll
        for (int o = NBLK / 2; o; o >>= 1) {
            if (tid < o) s[tid] += s[tid + o];
            __syncthreads();
        }
        if (tid == 0) out[0] = s[0] / (float)(Bq * Nn);
    }
}

// ---------------------------------------------------------------------------
extern "C" void kernel_launch(void* const* d_in, const int* in_sizes, int n_in,
                              void* d_out, int out_size) {
    const float* adj = (const float*)d_in[0];
    const float* emb = (const float*)d_in[1];

    static bool attr_done = false;
    if (!attr_done) {
        cudaFuncSetAttribute(k_main, cudaFuncAttributeMaxDynamicSharedMemorySize,
                             SMEM_BYTES);
        attr_done = true;
    }

    dim3 gp(Nn / 32, Bq);
    k_prep<<<gp, 256>>>(emb);
    dim3 gm(KSPLIT, Nn / TM, Bq);
    k_main<<<gm, 256, SMEM_BYTES>>>(adj, emb, (float*)d_out);
}